// round 14
// baseline (speedup 1.0000x reference)
#include <cuda_runtime.h>
#include <cuda_fp16.h>
#include <cstdint>
#include <math.h>

#define NROWS 10000
#define S_    20
#define D_    512
#define DOUT_ 512
#define ATTEN_ 64

// ---------------------------------------------------------------------------
// Scratch (device globals -- no allocations allowed)
// ---------------------------------------------------------------------------
__device__ uint32_t g_sv[NROWS * 256];        // self_vecs fp16 packed
__device__ uint32_t g_ns[NROWS * 256];        // neigh_sum fp16 packed
__device__ uint32_t g_ws[256 * DOUT_];        // self_weights fp16 [k2][n]
__device__ uint32_t g_wn[256 * DOUT_];        // neigh_weights fp16 [k2][n]
__device__ float    g_from_self[NROWS * DOUT_];
__device__ float    g_gates[NROWS * 2];
__device__ float    g_us[D_];
__device__ float    g_un[D_];
// dependency tracking (zeroed by prep each call)
__device__ int      g_panel_cnt[79];          // counts ROWS done per 128-row panel
__device__ int      g_self_flag[632];

// grid composition: groups of 10 = 8 reduce + 1 self-GEMM + 1 neigh-GEMM(lag 8)
#define NGROUPS   632
#define NLAG      8
#define GRID_ALL  (NGROUPS * 10 + NLAG)   // 6328

// GEMM geometry (single-chain fp16)
#define GK     512
#define GBK    32
#define GNITER (GK / GBK)        // 16
#define GBN    64
#define ASTR   20                // u32 per A row (16 + 4 pad)
#define APART  (128 * ASTR)      // 2560 u32
#define BSTR   (GBN + 8)         // 72
#define BPART  (16 * BSTR)       // 1152 u32
#define GBB    APART             // 2560
#define GSTG   (GBB + BPART)     // 3712 u32 / stage
#define GSMEM  (2 * GSTG * 4)    // 29696 bytes

// ---------------------------------------------------------------------------
// helpers
// ---------------------------------------------------------------------------
__device__ __forceinline__ uint32_t smem_u32(const void* p) {
    uint32_t a;
    asm("{ .reg .u64 t; cvta.to.shared.u64 t, %1; cvt.u32.u64 %0, t; }" : "=r"(a) : "l"(p));
    return a;
}
__device__ __forceinline__ uint32_t pack1h(float a, float b) {
    __half2 h = __floats2half2_rn(a, b);
    return *reinterpret_cast<uint32_t*>(&h);
}
__device__ __forceinline__ void mma16816(float* c, const uint32_t* a, const uint32_t* b) {
    asm volatile(
        "mma.sync.aligned.m16n8k16.row.col.f32.f16.f16.f32 "
        "{%0,%1,%2,%3}, {%4,%5,%6,%7}, {%8,%9}, {%0,%1,%2,%3};"
        : "+f"(c[0]), "+f"(c[1]), "+f"(c[2]), "+f"(c[3])
        : "r"(a[0]), "r"(a[1]), "r"(a[2]), "r"(a[3]), "r"(b[0]), "r"(b[1]));
}
#define CP16(dst, src, pr) \
    asm volatile("cp.async.cg.shared.global [%0], [%1], 16, %2;" :: "r"(dst), "l"(src), "r"(pr))
#define CP_COMMIT() asm volatile("cp.async.commit_group;" ::: "memory")
#define CP_WAIT1()  asm volatile("cp.async.wait_group 1;" ::: "memory")
#define CP_WAIT0()  asm volatile("cp.async.wait_group 0;" ::: "memory")

// ---------------------------------------------------------------------------
// 128x64 GEMM body: C = A @ B, single-chain fp16, fp32 accum, cp.async staged.
// ---------------------------------------------------------------------------
struct GemmAcc { float a[2][4][4]; };

__device__ __forceinline__ void gemm_body(
    const uint32_t* __restrict__ A_, const uint32_t* __restrict__ B_,
    uint32_t* s32, int m0, int n0, int M, GemmAcc& R) {

    uint32_t sb = smem_u32(s32);
    int tid  = threadIdx.x;
    int lane = tid & 31, wid = tid >> 5;
    int wm   = wid & 3, wn = wid >> 2;

    #pragma unroll
    for (int mt = 0; mt < 2; mt++)
        #pragma unroll
        for (int nt = 0; nt < 4; nt++)
            #pragma unroll
            for (int e = 0; e < 4; e++) R.a[mt][nt][e] = 0.f;

    auto stage = [&](int ic) {
        uint32_t base = sb + (ic & 1) * GSTG * 4;
        int k16 = ic * 16;
        #pragma unroll
        for (int j = 0; j < 2; j++) {
            int c = tid + j * 256;              // 0..511
            int row = c >> 2, q4 = (c & 3) * 4;
            const uint32_t* src = A_ + (size_t)(m0 + row) * 256 + k16 + q4;
            uint32_t dst = base + (uint32_t)(row * ASTR + q4) * 4;
            int pr = (m0 + row < M) ? 16 : 0;
            CP16(dst, src, pr);
        }
        {
            int k2 = tid >> 4, n4 = (tid & 15) * 4;
            const uint32_t* src = B_ + (size_t)(k16 + k2) * DOUT_ + n0 + n4;
            uint32_t dst = base + (uint32_t)(GBB + k2 * BSTR + n4) * 4;
            CP16(dst, src, 16);
        }
    };

    auto compute = [&](int p) {
        const uint32_t* base = s32 + p * GSTG;
        const uint32_t* Ax = base;
        const uint32_t* Bx = base + GBB;
        #pragma unroll
        for (int ks = 0; ks < 2; ks++) {
            int b8 = ks * 8;
            uint32_t af[2][4];
            #pragma unroll
            for (int mt = 0; mt < 2; mt++) {
                int row = wm * 32 + mt * 16 + (lane >> 2);
                int kc  = b8 + (lane & 3);
                af[mt][0] = Ax[row * ASTR + kc];
                af[mt][1] = Ax[(row + 8) * ASTR + kc];
                af[mt][2] = Ax[row * ASTR + kc + 4];
                af[mt][3] = Ax[(row + 8) * ASTR + kc + 4];
            }
            uint32_t bf[4][2];
            #pragma unroll
            for (int nt = 0; nt < 4; nt++) {
                int col = wn * 32 + nt * 8 + (lane >> 2);
                int kc  = b8 + (lane & 3);
                bf[nt][0] = Bx[kc * BSTR + col];
                bf[nt][1] = Bx[(kc + 4) * BSTR + col];
            }
            #pragma unroll
            for (int mt = 0; mt < 2; mt++)
                #pragma unroll
                for (int nt = 0; nt < 4; nt++)
                    mma16816(R.a[mt][nt], af[mt], bf[nt]);
        }
    };

    stage(0); CP_COMMIT();
    stage(1); CP_COMMIT();
    for (int ic = 0; ic < GNITER; ic++) {
        if (ic + 1 < GNITER) { CP_WAIT1(); } else { CP_WAIT0(); }
        __syncthreads();
        compute(ic & 1);
        __syncthreads();
        if (ic + 2 < GNITER) { stage(ic + 2); CP_COMMIT(); }
    }
}

// ---------------------------------------------------------------------------
// Prep kernel, role-dispatched (also resets dependency counters)
// ---------------------------------------------------------------------------
__global__ void __launch_bounds__(256)
prep_kernel(const float* __restrict__ self_atten,
            const float* __restrict__ neigh_atten,
            const float* __restrict__ v,
            const float* __restrict__ self_vecs,
            const float* __restrict__ self_weights,
            const float* __restrict__ neigh_weights) {
    int b = blockIdx.x, tid = threadIdx.x;
    if (b < 64) {
        if (b == 0) {
            for (int i = tid; i < 79; i += 256) g_panel_cnt[i] = 0;
            for (int i = tid; i < 632; i += 256) g_self_flag[i] = 0;
        }
        int wid  = (b * 256 + tid) >> 5;
        int lane = tid & 31;
        float v0 = v[lane], v1 = v[lane + 32];
        float s = self_atten[wid * ATTEN_ + lane]       * v0
                + self_atten[wid * ATTEN_ + lane + 32]  * v1;
        float n = neigh_atten[wid * ATTEN_ + lane]      * v0
                + neigh_atten[wid * ATTEN_ + lane + 32] * v1;
        #pragma unroll
        for (int o = 16; o > 0; o >>= 1) {
            s += __shfl_xor_sync(0xFFFFFFFFu, s, o);
            n += __shfl_xor_sync(0xFFFFFFFFu, n, o);
        }
        if (lane == 0) { g_us[wid] = s; g_un[wid] = n; }
    } else if (b < 5064) {
        int idx = (b - 64) * 256 + tid;            // float4 index
        int row = idx >> 7, j = idx & 127;
        float4 x = reinterpret_cast<const float4*>(self_vecs)[(size_t)row * 128 + j];
        *reinterpret_cast<uint2*>(&g_sv[(size_t)row * 256 + 2 * j]) =
            make_uint2(pack1h(x.x, x.y), pack1h(x.z, x.w));
    } else {
        bool isW = (b < 5576);
        const float* W = isW ? self_weights : neigh_weights;
        uint32_t* dst = isW ? g_ws : g_wn;
        int idx = ((b - (isW ? 5064 : 5576)) * 256 + tid);   // 0..131071
        int k2 = idx >> 9, n = idx & 511;
        float a = W[(size_t)(2 * k2) * DOUT_ + n];
        float c = W[(size_t)(2 * k2 + 1) * DOUT_ + n];
        dst[idx] = pack1h(a, c);
    }
}

// ---------------------------------------------------------------------------
// Neigh-GEMM + blend role body (tile index t = 0..631)
// ---------------------------------------------------------------------------
__device__ __forceinline__ void neigh_blend_tile(int t, uint32_t* s32,
                                                 float* __restrict__ out, int M) {
    int n0 = (t & 7) * GBN;
    int p  = t >> 3;                       // panel
    int m0 = p * 128;

    if (threadIdx.x == 0) {
        int target = min(128, M - 128 * p);
        while (atomicAdd(&g_panel_cnt[p], 0) < target) __nanosleep(100);
        __threadfence();
    }
    __syncthreads();

    GemmAcc R;
    gemm_body(g_ns, g_wn, s32, m0, n0, M, R);

    if (threadIdx.x == 0) {
        while (atomicAdd(&g_self_flag[t], 0) == 0) __nanosleep(100);
        __threadfence();
    }
    __syncthreads();

    int lane = threadIdx.x & 31, wid = threadIdx.x >> 5;
    int wm = wid & 3, wn = wid >> 2;
    #pragma unroll
    for (int mt = 0; mt < 2; mt++) {
        int r0 = m0 + wm * 32 + mt * 16 + (lane >> 2);
        int r1 = r0 + 8;
        float gs0 = 0.f, gn0 = 0.f, gs1 = 0.f, gn1 = 0.f;
        if (r0 < M) { gs0 = __ldcg(&g_gates[2 * r0]); gn0 = __ldcg(&g_gates[2 * r0 + 1]); }
        if (r1 < M) { gs1 = __ldcg(&g_gates[2 * r1]); gn1 = __ldcg(&g_gates[2 * r1 + 1]); }
        #pragma unroll
        for (int nt = 0; nt < 4; nt++) {
            int col = n0 + wn * 32 + nt * 8 + (lane & 3) * 2;
            if (r0 < M) {
                float2 fs = __ldcg(reinterpret_cast<const float2*>(&g_from_self[(size_t)r0 * DOUT_ + col]));
                float2 o;
                o.x = fmaxf(fmaf(gs0, fs.x, gn0 * R.a[mt][nt][0]), 0.f);
                o.y = fmaxf(fmaf(gs0, fs.y, gn0 * R.a[mt][nt][1]), 0.f);
                *reinterpret_cast<float2*>(&out[(size_t)r0 * DOUT_ + col]) = o;
            }
            if (r1 < M) {
                float2 fs = __ldcg(reinterpret_cast<const float2*>(&g_from_self[(size_t)r1 * DOUT_ + col]));
                float2 o;
                o.x = fmaxf(fmaf(gs1, fs.x, gn1 * R.a[mt][nt][2]), 0.f);
                o.y = fmaxf(fmaf(gs1, fs.y, gn1 * R.a[mt][nt][3]), 0.f);
                *reinterpret_cast<float2*>(&out[(size_t)r1 * DOUT_ + col]) = o;
            }
        }
    }
}

// ---------------------------------------------------------------------------
// Mega kernel. Group of 10 blocks:
//   rem 0..3,5..8 -> reduce+gate (2 rows each; bumps panel row-counter by 2)
//   rem 4         -> self-GEMM tile g (writes g_from_self, sets flag)
//   rem 9         -> neigh-GEMM+blend tile g-8 (skip if g<8)
// Tail blocks (bx >= NGROUPS*10) -> neigh tiles 624..631.
// All spin dependencies point strictly backward in blockIdx.
// ---------------------------------------------------------------------------
__global__ void __launch_bounds__(256)
mega_kernel(const float* __restrict__ neigh_vecs,
            const float* __restrict__ neigh_weight,
            const int*   __restrict__ neigh_column,
            const float* __restrict__ alpha,
            float*       __restrict__ out,
            int M) {
    extern __shared__ uint32_t s32[];
    int bx = blockIdx.x;

    if (bx >= NGROUPS * 10) {
        // tail: last NLAG neigh tiles
        neigh_blend_tile(NGROUPS - NLAG + (bx - NGROUPS * 10), s32, out, M);
        return;
    }

    int g   = bx / 10;
    int rem = bx % 10;

    if (rem == 9) {
        if (g >= NLAG) neigh_blend_tile(g - NLAG, s32, out, M);
        return;
    }

    if (rem == 4) {
        // ---------------- self-GEMM role ----------------
        int n0 = (g & 7) * GBN;
        int m0 = (g >> 3) * 128;
        GemmAcc R;
        gemm_body(g_sv, g_ws, s32, m0, n0, M, R);

        int lane = threadIdx.x & 31, wid = threadIdx.x >> 5;
        int wm = wid & 3, wn = wid >> 2;
        #pragma unroll
        for (int mt = 0; mt < 2; mt++) {
            int r0 = m0 + wm * 32 + mt * 16 + (lane >> 2);
            int r1 = r0 + 8;
            #pragma unroll
            for (int nt = 0; nt < 4; nt++) {
                int col = n0 + wn * 32 + nt * 8 + (lane & 3) * 2;
                if (r0 < M)
                    *reinterpret_cast<float2*>(&g_from_self[(size_t)r0 * DOUT_ + col]) =
                        make_float2(R.a[mt][nt][0], R.a[mt][nt][1]);
                if (r1 < M)
                    *reinterpret_cast<float2*>(&g_from_self[(size_t)r1 * DOUT_ + col]) =
                        make_float2(R.a[mt][nt][2], R.a[mt][nt][3]);
            }
        }
        __threadfence();
        __syncthreads();
        if (threadIdx.x == 0) atomicExch(&g_self_flag[g], 1);
        return;
    }

    // ---------------- reduce + gate role (2 rows, shuffle softmax) --------
    int rb = g * 8 + (rem < 4 ? rem : rem - 1);
    if (rb >= NROWS / 2) return;

    int half = threadIdx.x >> 7;
    int t    = threadIdx.x & 127;
    int lane = t & 31;
    int row  = rb * 2 + half;

    // per-warp redundant softmax, all in registers
    float we = 0.f, nw = 0.f;
    if (lane < S_) {
        we = expf(alpha[__ldg(&neigh_column[row * S_ + lane])]);
        nw = __ldg(&neigh_weight[row * S_ + lane]);
    }
    float ssum = we;
    #pragma unroll
    for (int o = 16; o > 0; o >>= 1) ssum += __shfl_xor_sync(0xFFFFFFFFu, ssum, o);
    float wfull = nw * we / ssum;              // lanes >= S_ hold 0

    // main weighted reduction: 4-wide load batches, no syncs
    const float4* nv = reinterpret_cast<const float4*>(neigh_vecs) + (size_t)row * S_ * 128;
    float4 acc = make_float4(0.f, 0.f, 0.f, 0.f);
    #pragma unroll
    for (int s = 0; s < S_; s += 4) {
        float4 x0 = nv[(s + 0) * 128 + t];
        float4 x1 = nv[(s + 1) * 128 + t];
        float4 x2 = nv[(s + 2) * 128 + t];
        float4 x3 = nv[(s + 3) * 128 + t];
        float w0 = __shfl_sync(0xFFFFFFFFu, wfull, s + 0);
        float w1 = __shfl_sync(0xFFFFFFFFu, wfull, s + 1);
        float w2 = __shfl_sync(0xFFFFFFFFu, wfull, s + 2);
        float w3 = __shfl_sync(0xFFFFFFFFu, wfull, s + 3);
        acc.x = fmaf(x0.x, w0, acc.x); acc.y = fmaf(x0.y, w0, acc.y);
        acc.z = fmaf(x0.z, w0, acc.z); acc.w = fmaf(x0.w, w0, acc.w);
        acc.x = fmaf(x1.x, w1, acc.x); acc.y = fmaf(x1.y, w1, acc.y);
        acc.z = fmaf(x1.z, w1, acc.z); acc.w = fmaf(x1.w, w1, acc.w);
        acc.x = fmaf(x2.x, w2, acc.x); acc.y = fmaf(x2.y, w2, acc.y);
        acc.z = fmaf(x2.z, w2, acc.z); acc.w = fmaf(x2.w, w2, acc.w);
        acc.x = fmaf(x3.x, w3, acc.x); acc.y = fmaf(x3.y, w3, acc.y);
        acc.z = fmaf(x3.z, w3, acc.z); acc.w = fmaf(x3.w, w3, acc.w);
    }

    // write packed fp16 neigh_sum
    *reinterpret_cast<uint2*>(&g_ns[(size_t)row * 256 + 2 * t]) =
        make_uint2(pack1h(acc.x, acc.y), pack1h(acc.z, acc.w));

    // gate dot products (self side from fp16-packed g_sv)
    float4 un = reinterpret_cast<const float4*>(g_un)[t];
    float4 us = reinterpret_cast<const float4*>(g_us)[t];
    uint2 svp = *reinterpret_cast<const uint2*>(&g_sv[(size_t)row * 256 + 2 * t]);
    float2 sv01 = __half22float2(*reinterpret_cast<__half2*>(&svp.x));
    float2 sv23 = __half22float2(*reinterpret_cast<__half2*>(&svp.y));
    float p = acc.x * un.x + acc.y * un.y + acc.z * un.z + acc.w * un.w;
    float q = sv01.x * us.x + sv01.y * us.y + sv23.x * us.z + sv23.y * us.w;
    #pragma unroll
    for (int o = 16; o > 0; o >>= 1) {
        p += __shfl_xor_sync(0xFFFFFFFFu, p, o);
        q += __shfl_xor_sync(0xFFFFFFFFu, q, o);
    }
    float* red = reinterpret_cast<float*>(s32);   // [2][4][2]
    if (lane == 0) { red[(half * 4 + (t >> 5)) * 2] = p; red[(half * 4 + (t >> 5)) * 2 + 1] = q; }
    __syncthreads();
    if (t == 0) {
        float P = 0.f, Q = 0.f;
        #pragma unroll
        for (int i = 0; i < 4; i++) { P += red[(half * 4 + i) * 2]; Q += red[(half * 4 + i) * 2 + 1]; }
        float a_s = expf(tanhf(2.f * Q));
        float a_n = expf(tanhf(P + Q));
        float iv = 1.f / (a_s + a_n);
        g_gates[2 * row]     = a_s * iv;
        g_gates[2 * row + 1] = a_n * iv;
    }

    // release: both rows of this block live in the same panel
    __threadfence();
    __syncthreads();
    if (threadIdx.x == 0) atomicAdd(&g_panel_cnt[rb >> 6], 2);
}

// ---------------------------------------------------------------------------
extern "C" void kernel_launch(void* const* d_in, const int* in_sizes, int n_in,
                              void* d_out, int out_size) {
    const float* self_vecs     = (const float*)d_in[0];
    const float* neigh_vecs    = (const float*)d_in[1];
    const float* neigh_weight  = (const float*)d_in[2];
    const int*   neigh_column  = (const int*)  d_in[3];
    const float* neigh_weights = (const float*)d_in[4];
    const float* self_weights  = (const float*)d_in[5];
    const float* alpha         = (const float*)d_in[6];
    const float* self_atten    = (const float*)d_in[7];
    const float* neigh_atten   = (const float*)d_in[8];
    const float* v             = (const float*)d_in[9];
    float* out = (float*)d_out;

    cudaFuncSetAttribute(mega_kernel, cudaFuncAttributeMaxDynamicSharedMemorySize, GSMEM);

    // 0. fused prep: u-vectors + fp16 packs + counter reset
    prep_kernel<<<6088, 256>>>(self_atten, neigh_atten, v,
                               self_vecs, self_weights, neigh_weights);

    // 1. fully fused with interleaved neigh-GEMM (lag-8 schedule)
    mega_kernel<<<GRID_ALL, 256, GSMEM>>>(neigh_vecs, neigh_weight, neigh_column,
                                          alpha, out, NROWS);
}

// round 15
// speedup vs baseline: 1.0198x; 1.0198x over previous
#include <cuda_runtime.h>
#include <cuda_fp16.h>
#include <cstdint>
#include <math.h>

#define NROWS 10000
#define S_    20
#define D_    512
#define DOUT_ 512
#define ATTEN_ 64

// ---------------------------------------------------------------------------
// Scratch (device globals -- no allocations allowed)
// ---------------------------------------------------------------------------
__device__ uint32_t g_sv[NROWS * 256];        // self_vecs fp16 packed (by reduce role)
__device__ uint32_t g_ns[NROWS * 256];        // neigh_sum fp16 packed
__device__ uint32_t g_ws[256 * DOUT_];        // self_weights fp16 [k2][n]
__device__ uint32_t g_wn[256 * DOUT_];        // neigh_weights fp16 [k2][n]
__device__ uint32_t g_fs[NROWS * 256];        // from_self fp16 packed (col pairs)
__device__ float    g_gates[NROWS * 2];
__device__ float    g_us[D_];
__device__ float    g_un[D_];
// dependency tracking (zeroed by prep each call)
__device__ int      g_panel_cnt[79];          // ROWS done per 128-row panel
__device__ int      g_self_flag[632];

// grid composition: R12 schedule — 8 reduce + 1 self-GEMM per 9; neigh tail
#define NGROUPS   632
#define FRONT     (NGROUPS * 9)       // 5688
#define GRID_ALL  (FRONT + NGROUPS)   // 6320

// GEMM geometry (single-chain fp16)
#define GK     512
#define GBK    32
#define GNITER (GK / GBK)        // 16
#define GBN    64
#define ASTR   20                // u32 per A row (16 + 4 pad)
#define APART  (128 * ASTR)      // 2560 u32
#define BSTR   (GBN + 8)         // 72
#define BPART  (16 * BSTR)       // 1152 u32
#define GBB    APART             // 2560
#define GSTG   (GBB + BPART)     // 3712 u32 / stage
#define GSMEM  (2 * GSTG * 4)    // 29696 bytes

// ---------------------------------------------------------------------------
// helpers
// ---------------------------------------------------------------------------
__device__ __forceinline__ uint32_t smem_u32(const void* p) {
    uint32_t a;
    asm("{ .reg .u64 t; cvta.to.shared.u64 t, %1; cvt.u32.u64 %0, t; }" : "=r"(a) : "l"(p));
    return a;
}
__device__ __forceinline__ uint32_t pack1h(float a, float b) {
    __half2 h = __floats2half2_rn(a, b);
    return *reinterpret_cast<uint32_t*>(&h);
}
__device__ __forceinline__ float2 unpack1h(uint32_t u) {
    return __half22float2(*reinterpret_cast<__half2*>(&u));
}
__device__ __forceinline__ void mma16816(float* c, const uint32_t* a, const uint32_t* b) {
    asm volatile(
        "mma.sync.aligned.m16n8k16.row.col.f32.f16.f16.f32 "
        "{%0,%1,%2,%3}, {%4,%5,%6,%7}, {%8,%9}, {%0,%1,%2,%3};"
        : "+f"(c[0]), "+f"(c[1]), "+f"(c[2]), "+f"(c[3])
        : "r"(a[0]), "r"(a[1]), "r"(a[2]), "r"(a[3]), "r"(b[0]), "r"(b[1]));
}
#define CP16(dst, src, pr) \
    asm volatile("cp.async.cg.shared.global [%0], [%1], 16, %2;" :: "r"(dst), "l"(src), "r"(pr))
#define CP_COMMIT() asm volatile("cp.async.commit_group;" ::: "memory")
#define CP_WAIT1()  asm volatile("cp.async.wait_group 1;" ::: "memory")
#define CP_WAIT0()  asm volatile("cp.async.wait_group 0;" ::: "memory")

// ---------------------------------------------------------------------------
// 128x64 GEMM body: C = A @ B, single-chain fp16, fp32 accum, cp.async staged.
// ---------------------------------------------------------------------------
struct GemmAcc { float a[2][4][4]; };

__device__ __forceinline__ void gemm_body(
    const uint32_t* __restrict__ A_, const uint32_t* __restrict__ B_,
    uint32_t* s32, int m0, int n0, int M, GemmAcc& R) {

    uint32_t sb = smem_u32(s32);
    int tid  = threadIdx.x;
    int lane = tid & 31, wid = tid >> 5;
    int wm   = wid & 3, wn = wid >> 2;

    #pragma unroll
    for (int mt = 0; mt < 2; mt++)
        #pragma unroll
        for (int nt = 0; nt < 4; nt++)
            #pragma unroll
            for (int e = 0; e < 4; e++) R.a[mt][nt][e] = 0.f;

    auto stage = [&](int ic) {
        uint32_t base = sb + (ic & 1) * GSTG * 4;
        int k16 = ic * 16;
        #pragma unroll
        for (int j = 0; j < 2; j++) {
            int c = tid + j * 256;              // 0..511
            int row = c >> 2, q4 = (c & 3) * 4;
            const uint32_t* src = A_ + (size_t)(m0 + row) * 256 + k16 + q4;
            uint32_t dst = base + (uint32_t)(row * ASTR + q4) * 4;
            int pr = (m0 + row < M) ? 16 : 0;
            CP16(dst, src, pr);
        }
        {
            int k2 = tid >> 4, n4 = (tid & 15) * 4;
            const uint32_t* src = B_ + (size_t)(k16 + k2) * DOUT_ + n0 + n4;
            uint32_t dst = base + (uint32_t)(GBB + k2 * BSTR + n4) * 4;
            CP16(dst, src, 16);
        }
    };

    auto compute = [&](int p) {
        const uint32_t* base = s32 + p * GSTG;
        const uint32_t* Ax = base;
        const uint32_t* Bx = base + GBB;
        #pragma unroll
        for (int ks = 0; ks < 2; ks++) {
            int b8 = ks * 8;
            uint32_t af[2][4];
            #pragma unroll
            for (int mt = 0; mt < 2; mt++) {
                int row = wm * 32 + mt * 16 + (lane >> 2);
                int kc  = b8 + (lane & 3);
                af[mt][0] = Ax[row * ASTR + kc];
                af[mt][1] = Ax[(row + 8) * ASTR + kc];
                af[mt][2] = Ax[row * ASTR + kc + 4];
                af[mt][3] = Ax[(row + 8) * ASTR + kc + 4];
            }
            uint32_t bf[4][2];
            #pragma unroll
            for (int nt = 0; nt < 4; nt++) {
                int col = wn * 32 + nt * 8 + (lane >> 2);
                int kc  = b8 + (lane & 3);
                bf[nt][0] = Bx[kc * BSTR + col];
                bf[nt][1] = Bx[(kc + 4) * BSTR + col];
            }
            #pragma unroll
            for (int mt = 0; mt < 2; mt++)
                #pragma unroll
                for (int nt = 0; nt < 4; nt++)
                    mma16816(R.a[mt][nt], af[mt], bf[nt]);
        }
    };

    stage(0); CP_COMMIT();
    stage(1); CP_COMMIT();
    for (int ic = 0; ic < GNITER; ic++) {
        if (ic + 1 < GNITER) { CP_WAIT1(); } else { CP_WAIT0(); }
        __syncthreads();
        compute(ic & 1);
        __syncthreads();
        if (ic + 2 < GNITER) { stage(ic + 2); CP_COMMIT(); }
    }
}

// ---------------------------------------------------------------------------
// Prep kernel: u-vectors + counter reset + weight packs only (sv moved to mega)
//   [0,64):      prep_u (block 0 zeroes counters/flags)
//   [64,576):    pack self_weights  -> g_ws
//   [576,1088):  pack neigh_weights -> g_wn
// ---------------------------------------------------------------------------
__global__ void __launch_bounds__(256)
prep_kernel(const float* __restrict__ self_atten,
            const float* __restrict__ neigh_atten,
            const float* __restrict__ v,
            const float* __restrict__ self_weights,
            const float* __restrict__ neigh_weights) {
    int b = blockIdx.x, tid = threadIdx.x;
    if (b < 64) {
        if (b == 0) {
            for (int i = tid; i < 79; i += 256) g_panel_cnt[i] = 0;
            for (int i = tid; i < 632; i += 256) g_self_flag[i] = 0;
        }
        int wid  = (b * 256 + tid) >> 5;
        int lane = tid & 31;
        float v0 = v[lane], v1 = v[lane + 32];
        float s = self_atten[wid * ATTEN_ + lane]       * v0
                + self_atten[wid * ATTEN_ + lane + 32]  * v1;
        float n = neigh_atten[wid * ATTEN_ + lane]      * v0
                + neigh_atten[wid * ATTEN_ + lane + 32] * v1;
        #pragma unroll
        for (int o = 16; o > 0; o >>= 1) {
            s += __shfl_xor_sync(0xFFFFFFFFu, s, o);
            n += __shfl_xor_sync(0xFFFFFFFFu, n, o);
        }
        if (lane == 0) { g_us[wid] = s; g_un[wid] = n; }
    } else {
        bool isW = (b < 576);
        const float* W = isW ? self_weights : neigh_weights;
        uint32_t* dst = isW ? g_ws : g_wn;
        int idx = ((b - (isW ? 64 : 576)) * 256 + tid);   // 0..131071
        int k2 = idx >> 9, n = idx & 511;
        float a = W[(size_t)(2 * k2) * DOUT_ + n];
        float c = W[(size_t)(2 * k2 + 1) * DOUT_ + n];
        dst[idx] = pack1h(a, c);
    }
}

// ---------------------------------------------------------------------------
// Mega kernel, three roles (R12 schedule):
//   bx < FRONT, bx%9==4 -> self-GEMM (waits panel cnt; writes g_fs fp16, flag)
//   bx < FRONT, else    -> reduce+gate (2 rows; also packs g_sv; bumps cnt +2)
//   bx >= FRONT         -> neigh-GEMM + blend (waits panel cnt + self flag)
// ---------------------------------------------------------------------------
__global__ void __launch_bounds__(256)
mega_kernel(const float* __restrict__ neigh_vecs,
            const float* __restrict__ neigh_weight,
            const int*   __restrict__ neigh_column,
            const float* __restrict__ alpha,
            const float* __restrict__ self_vecs,
            float*       __restrict__ out,
            int M) {
    extern __shared__ uint32_t s32[];
    int bx = blockIdx.x;

    if (bx >= FRONT) {
        // ---------------- neigh-GEMM + blend role ----------------
        int g  = bx - FRONT;                   // 0..631
        int n0 = (g & 7) * GBN;
        int p  = g >> 3;                       // panel
        int m0 = p * 128;

        if (threadIdx.x == 0) {
            int target = min(128, M - 128 * p);
            while (atomicAdd(&g_panel_cnt[p], 0) < target) __nanosleep(100);
            __threadfence();
        }
        __syncthreads();

        GemmAcc R;
        gemm_body(g_ns, g_wn, s32, m0, n0, M, R);

        if (threadIdx.x == 0) {
            while (atomicAdd(&g_self_flag[g], 0) == 0) __nanosleep(100);
            __threadfence();
        }
        __syncthreads();

        int lane = threadIdx.x & 31, wid = threadIdx.x >> 5;
        int wm = wid & 3, wn = wid >> 2;
        #pragma unroll
        for (int mt = 0; mt < 2; mt++) {
            int r0 = m0 + wm * 32 + mt * 16 + (lane >> 2);
            int r1 = r0 + 8;
            float gs0 = 0.f, gn0 = 0.f, gs1 = 0.f, gn1 = 0.f;
            if (r0 < M) { gs0 = __ldcg(&g_gates[2 * r0]); gn0 = __ldcg(&g_gates[2 * r0 + 1]); }
            if (r1 < M) { gs1 = __ldcg(&g_gates[2 * r1]); gn1 = __ldcg(&g_gates[2 * r1 + 1]); }
            #pragma unroll
            for (int nt = 0; nt < 4; nt++) {
                int col = n0 + wn * 32 + nt * 8 + (lane & 3) * 2;
                if (r0 < M) {
                    float2 fs = unpack1h(__ldcg(&g_fs[(size_t)r0 * 256 + (col >> 1)]));
                    float2 o;
                    o.x = fmaxf(fmaf(gs0, fs.x, gn0 * R.a[mt][nt][0]), 0.f);
                    o.y = fmaxf(fmaf(gs0, fs.y, gn0 * R.a[mt][nt][1]), 0.f);
                    *reinterpret_cast<float2*>(&out[(size_t)r0 * DOUT_ + col]) = o;
                }
                if (r1 < M) {
                    float2 fs = unpack1h(__ldcg(&g_fs[(size_t)r1 * 256 + (col >> 1)]));
                    float2 o;
                    o.x = fmaxf(fmaf(gs1, fs.x, gn1 * R.a[mt][nt][2]), 0.f);
                    o.y = fmaxf(fmaf(gs1, fs.y, gn1 * R.a[mt][nt][3]), 0.f);
                    *reinterpret_cast<float2*>(&out[(size_t)r1 * DOUT_ + col]) = o;
                }
            }
        }
        return;
    }

    int rem = bx % 9;
    if (rem == 4) {
        // ---------------- self-GEMM role (now waits on its panel) ---------
        int g  = bx / 9;                       // 0..631
        int n0 = (g & 7) * GBN;
        int p  = g >> 3;
        int m0 = p * 128;

        if (threadIdx.x == 0) {
            int target = min(128, M - 128 * p);
            while (atomicAdd(&g_panel_cnt[p], 0) < target) __nanosleep(100);
            __threadfence();
        }
        __syncthreads();

        GemmAcc R;
        gemm_body(g_sv, g_ws, s32, m0, n0, M, R);

        int lane = threadIdx.x & 31, wid = threadIdx.x >> 5;
        int wm = wid & 3, wn = wid >> 2;
        #pragma unroll
        for (int mt = 0; mt < 2; mt++) {
            int r0 = m0 + wm * 32 + mt * 16 + (lane >> 2);
            int r1 = r0 + 8;
            #pragma unroll
            for (int nt = 0; nt < 4; nt++) {
                int col = n0 + wn * 32 + nt * 8 + (lane & 3) * 2;
                if (r0 < M)
                    g_fs[(size_t)r0 * 256 + (col >> 1)] = pack1h(R.a[mt][nt][0], R.a[mt][nt][1]);
                if (r1 < M)
                    g_fs[(size_t)r1 * 256 + (col >> 1)] = pack1h(R.a[mt][nt][2], R.a[mt][nt][3]);
            }
        }
        __threadfence();
        __syncthreads();
        if (threadIdx.x == 0) atomicExch(&g_self_flag[g], 1);
        return;
    }

    // ---------------- reduce + gate role (2 rows, shuffle softmax) --------
    int rb = (bx / 9) * 8 + (rem < 4 ? rem : rem - 1);
    if (rb >= NROWS / 2) return;

    int half = threadIdx.x >> 7;
    int t    = threadIdx.x & 127;
    int lane = t & 31;
    int row  = rb * 2 + half;

    // per-warp redundant softmax, all in registers
    float we = 0.f, nw = 0.f;
    if (lane < S_) {
        we = expf(alpha[__ldg(&neigh_column[row * S_ + lane])]);
        nw = __ldg(&neigh_weight[row * S_ + lane]);
    }
    float ssum = we;
    #pragma unroll
    for (int o = 16; o > 0; o >>= 1) ssum += __shfl_xor_sync(0xFFFFFFFFu, ssum, o);
    float wfull = nw * we / ssum;              // lanes >= S_ hold 0

    // main weighted reduction: 4-wide load batches, no syncs
    const float4* nv = reinterpret_cast<const float4*>(neigh_vecs) + (size_t)row * S_ * 128;
    float4 acc = make_float4(0.f, 0.f, 0.f, 0.f);
    #pragma unroll
    for (int s = 0; s < S_; s += 4) {
        float4 x0 = nv[(s + 0) * 128 + t];
        float4 x1 = nv[(s + 1) * 128 + t];
        float4 x2 = nv[(s + 2) * 128 + t];
        float4 x3 = nv[(s + 3) * 128 + t];
        float w0 = __shfl_sync(0xFFFFFFFFu, wfull, s + 0);
        float w1 = __shfl_sync(0xFFFFFFFFu, wfull, s + 1);
        float w2 = __shfl_sync(0xFFFFFFFFu, wfull, s + 2);
        float w3 = __shfl_sync(0xFFFFFFFFu, wfull, s + 3);
        acc.x = fmaf(x0.x, w0, acc.x); acc.y = fmaf(x0.y, w0, acc.y);
        acc.z = fmaf(x0.z, w0, acc.z); acc.w = fmaf(x0.w, w0, acc.w);
        acc.x = fmaf(x1.x, w1, acc.x); acc.y = fmaf(x1.y, w1, acc.y);
        acc.z = fmaf(x1.z, w1, acc.z); acc.w = fmaf(x1.w, w1, acc.w);
        acc.x = fmaf(x2.x, w2, acc.x); acc.y = fmaf(x2.y, w2, acc.y);
        acc.z = fmaf(x2.z, w2, acc.z); acc.w = fmaf(x2.w, w2, acc.w);
        acc.x = fmaf(x3.x, w3, acc.x); acc.y = fmaf(x3.y, w3, acc.y);
        acc.z = fmaf(x3.z, w3, acc.z); acc.w = fmaf(x3.w, w3, acc.w);
    }

    // write packed fp16 neigh_sum
    *reinterpret_cast<uint2*>(&g_ns[(size_t)row * 256 + 2 * t]) =
        make_uint2(pack1h(acc.x, acc.y), pack1h(acc.z, acc.w));

    // read fp32 self_vecs once: gate q-dot + emit packed g_sv row
    float4 sv = reinterpret_cast<const float4*>(self_vecs)[(size_t)row * 128 + t];
    *reinterpret_cast<uint2*>(&g_sv[(size_t)row * 256 + 2 * t]) =
        make_uint2(pack1h(sv.x, sv.y), pack1h(sv.z, sv.w));

    float4 un = reinterpret_cast<const float4*>(g_un)[t];
    float4 us = reinterpret_cast<const float4*>(g_us)[t];
    float p = acc.x * un.x + acc.y * un.y + acc.z * un.z + acc.w * un.w;
    float q = sv.x  * us.x + sv.y  * us.y + sv.z  * us.z + sv.w  * us.w;
    #pragma unroll
    for (int o = 16; o > 0; o >>= 1) {
        p += __shfl_xor_sync(0xFFFFFFFFu, p, o);
        q += __shfl_xor_sync(0xFFFFFFFFu, q, o);
    }
    float* red = reinterpret_cast<float*>(s32);   // [2][4][2]
    if (lane == 0) { red[(half * 4 + (t >> 5)) * 2] = p; red[(half * 4 + (t >> 5)) * 2 + 1] = q; }
    __syncthreads();
    if (t == 0) {
        float P = 0.f, Q = 0.f;
        #pragma unroll
        for (int i = 0; i < 4; i++) { P += red[(half * 4 + i) * 2]; Q += red[(half * 4 + i) * 2 + 1]; }
        float a_s = expf(tanhf(2.f * Q));
        float a_n = expf(tanhf(P + Q));
        float iv = 1.f / (a_s + a_n);
        g_gates[2 * row]     = a_s * iv;
        g_gates[2 * row + 1] = a_n * iv;
    }

    // release: both rows of this block live in the same panel
    __threadfence();
    __syncthreads();
    if (threadIdx.x == 0) atomicAdd(&g_panel_cnt[rb >> 6], 2);
}

// ---------------------------------------------------------------------------
extern "C" void kernel_launch(void* const* d_in, const int* in_sizes, int n_in,
                              void* d_out, int out_size) {
    const float* self_vecs     = (const float*)d_in[0];
    const float* neigh_vecs    = (const float*)d_in[1];
    const float* neigh_weight  = (const float*)d_in[2];
    const int*   neigh_column  = (const int*)  d_in[3];
    const float* neigh_weights = (const float*)d_in[4];
    const float* self_weights  = (const float*)d_in[5];
    const float* alpha         = (const float*)d_in[6];
    const float* self_atten    = (const float*)d_in[7];
    const float* neigh_atten   = (const float*)d_in[8];
    const float* v             = (const float*)d_in[9];
    float* out = (float*)d_out;

    cudaFuncSetAttribute(mega_kernel, cudaFuncAttributeMaxDynamicSharedMemorySize, GSMEM);

    // 0. small prep: u-vectors + weight packs + counter reset (~12 MB traffic)
    prep_kernel<<<1088, 256>>>(self_atten, neigh_atten, v,
                               self_weights, neigh_weights);

    // 1. fully fused: reduce+gate(+sv pack) | self-GEMM | neigh-GEMM+blend
    mega_kernel<<<GRID_ALL, 256, GSMEM>>>(neigh_vecs, neigh_weight, neigh_column,
                                          alpha, self_vecs, out, NROWS);
}